// round 3
// baseline (speedup 1.0000x reference)
#include <cuda_runtime.h>
#include <math.h>

#define NN   50000
#define DH   128
#define DOUT 57
#define TOTE (800000 + NN)

// -------- scratch (__device__ globals; no allocation allowed) --------
__device__ float4 g_h4[NN * 32];   // GEMM output h (both layers)  [N,128]
__device__ float4 g_t4[NN * 32];   // aggregation output            [N,128]
__device__ float  g_as[NN];        // alpha_src per node
__device__ float  g_ad[NN];        // alpha_dst per node
__device__ int    g_deg[NN];
__device__ int    g_off[NN + 1];
__device__ int    g_cur[NN];
__device__ int    g_srcs[TOTE];    // CSR (by dst): src node per edge

// ============================ CSR build ============================
// edge_index is int32 (JAX default x64-disabled downcasts jnp.int64 -> int32).
__global__ void k_init_deg() {
    int n = blockIdx.x * blockDim.x + threadIdx.x;
    if (n < NN) g_deg[n] = 1;      // +1 = self loop
}

__global__ void k_count(const int* __restrict__ ei, int E) {
    int e = blockIdx.x * blockDim.x + threadIdx.x;
    if (e < E) {
        int d = ei[E + e];
        if (d >= 0 && d < NN) atomicAdd(&g_deg[d], 1);
    }
}

// single-block exclusive scan of g_deg -> g_off (50001 entries)
__global__ void k_scan() {
    __shared__ int sums[1024];
    const int n = NN;
    int tid = threadIdx.x;
    const int chunk = (n + 1023) / 1024;
    int base = tid * chunk;
    int s = 0;
    for (int i = 0; i < chunk; ++i) {
        int idx = base + i;
        if (idx < n) s += g_deg[idx];
    }
    sums[tid] = s;
    __syncthreads();
    for (int d = 1; d < 1024; d <<= 1) {
        int v = (tid >= d) ? sums[tid - d] : 0;
        __syncthreads();
        sums[tid] += v;
        __syncthreads();
    }
    int run = (tid == 0) ? 0 : sums[tid - 1];
    for (int i = 0; i < chunk; ++i) {
        int idx = base + i;
        if (idx < n) { g_off[idx] = run; run += g_deg[idx]; }
    }
    if (tid == 1023) g_off[n] = sums[1023];
}

__global__ void k_self() {
    int n = blockIdx.x * blockDim.x + threadIdx.x;
    if (n < NN) {
        int p = g_off[n];
        g_srcs[p] = n;             // self loop in slot 0
        g_cur[n] = p + 1;
    }
}

__global__ void k_scatter(const int* __restrict__ ei, int E) {
    int e = blockIdx.x * blockDim.x + threadIdx.x;
    if (e < E) {
        int d = ei[E + e];
        int s = ei[e];
        if (d >= 0 && d < NN && s >= 0 && s < NN) {
            int p = atomicAdd(&g_cur[d], 1);
            if (p >= 0 && p < TOTE) g_srcs[p] = s;
        }
    }
}

// ============================ GEMM (fused alpha) ============================
// C[M,Wn] = act(A)[M,128] @ W[128,Wn]   (M = NN)
// MODE 0: A=ext(x),  C=g_h4, no relu, fused alpha (a1)
// MODE 1: A=g_t4,    C=g_h4, relu-in, fused alpha (a2)
// MODE 2: A=g_t4,    C=ext(d_out), Wn=57, +bias
// Static smem: 64 k-rows x 128 cols of W = 32 KB; two K-halves.
template <int MODE>
__global__ void gemm_kernel(const float4* __restrict__ Aext,
                            const float* __restrict__ W,
                            const float* __restrict__ avs,
                            const float* __restrict__ avd,
                            const float* __restrict__ bias,
                            float* __restrict__ Cext) {
    constexpr int  Wn   = (MODE == 2) ? DOUT : DH;
    constexpr bool RELU = (MODE == 1);
    __shared__ float4 Ws4[64 * 32];               // [64 k-rows][128 cols] = 32 KB

    const float4* A = (MODE == 0) ? Aext : g_t4;

    int tid = threadIdx.x;                        // 256 threads
    int tx = tid & 31, ty = tid >> 5;
    int rowBase = blockIdx.x * 64 + ty * 8;
    int rmax = NN - rowBase;                      // #valid rows for this warp (warp-uniform)

    float4 acc[8];
#pragma unroll
    for (int i = 0; i < 8; ++i) acc[i] = make_float4(0.f, 0.f, 0.f, 0.f);

    for (int half = 0; half < 2; ++half) {
        for (int i = tid; i < 64 * DH; i += 256) {
            int k = i >> 7, c = i & 127;
            float v = (c < Wn) ? W[(half * 64 + k) * Wn + c] : 0.f;
            ((float*)Ws4)[i] = v;
        }
        __syncthreads();

#pragma unroll 2
        for (int k4 = 0; k4 < 16; ++k4) {
            float4 w0 = Ws4[(k4 * 4 + 0) * 32 + tx];
            float4 w1 = Ws4[(k4 * 4 + 1) * 32 + tx];
            float4 w2 = Ws4[(k4 * 4 + 2) * 32 + tx];
            float4 w3 = Ws4[(k4 * 4 + 3) * 32 + tx];
#pragma unroll
            for (int i = 0; i < 8; ++i) {
                if (i < rmax) {
                    float4 a = A[(rowBase + i) * 32 + half * 16 + k4];
                    if (RELU) {
                        a.x = fmaxf(a.x, 0.f); a.y = fmaxf(a.y, 0.f);
                        a.z = fmaxf(a.z, 0.f); a.w = fmaxf(a.w, 0.f);
                    }
                    acc[i].x = fmaf(a.x, w0.x, fmaf(a.y, w1.x, fmaf(a.z, w2.x, fmaf(a.w, w3.x, acc[i].x))));
                    acc[i].y = fmaf(a.x, w0.y, fmaf(a.y, w1.y, fmaf(a.z, w2.y, fmaf(a.w, w3.y, acc[i].y))));
                    acc[i].z = fmaf(a.x, w0.z, fmaf(a.y, w1.z, fmaf(a.z, w2.z, fmaf(a.w, w3.z, acc[i].z))));
                    acc[i].w = fmaf(a.x, w0.w, fmaf(a.y, w1.w, fmaf(a.z, w2.w, fmaf(a.w, w3.w, acc[i].w))));
                }
            }
        }
        __syncthreads();
    }

    if (MODE < 2) {
        float as0 = avs[4 * tx + 0], as1 = avs[4 * tx + 1], as2 = avs[4 * tx + 2], as3 = avs[4 * tx + 3];
        float ad0 = avd[4 * tx + 0], ad1 = avd[4 * tx + 1], ad2 = avd[4 * tx + 2], ad3 = avd[4 * tx + 3];
#pragma unroll
        for (int i = 0; i < 8; ++i) {
            if (i < rmax) {
                int row = rowBase + i;
                g_h4[row * 32 + tx] = acc[i];
                float ps = acc[i].x * as0 + acc[i].y * as1 + acc[i].z * as2 + acc[i].w * as3;
                float pd = acc[i].x * ad0 + acc[i].y * ad1 + acc[i].z * ad2 + acc[i].w * ad3;
#pragma unroll
                for (int o = 16; o; o >>= 1) {
                    ps += __shfl_xor_sync(0xffffffffu, ps, o);
                    pd += __shfl_xor_sync(0xffffffffu, pd, o);
                }
                if (tx == 0) { g_as[row] = ps; g_ad[row] = pd; }
            }
        }
    } else {
#pragma unroll
        for (int i = 0; i < 8; ++i) {
            if (i < rmax) {
                int row = rowBase + i;
                float v[4] = {acc[i].x, acc[i].y, acc[i].z, acc[i].w};
#pragma unroll
                for (int j = 0; j < 4; ++j) {
                    int col = 4 * tx + j;
                    if (col < DOUT) Cext[row * DOUT + col] = v[j] + bias[col];
                }
            }
        }
    }
}

// ==================== segment softmax + aggregation ====================
// one warp per destination node; out = g_t4 = segsum(w * h[src]) + bias
__global__ void agg_kernel(const float* __restrict__ bias) {
    int w = (blockIdx.x * blockDim.x + threadIdx.x) >> 5;
    if (w >= NN) return;
    int lane = threadIdx.x & 31;
    int beg = g_off[w], end = g_off[w + 1];
    float adn = g_ad[w];

    // pass 1: segment max of leaky_relu(e)
    float m = -INFINITY;
    for (int j = beg + lane; j < end; j += 32) {
        float e = g_as[g_srcs[j]] + adn;
        e = (e > 0.f) ? e : 0.2f * e;
        m = fmaxf(m, e);
    }
#pragma unroll
    for (int o = 16; o; o >>= 1) m = fmaxf(m, __shfl_xor_sync(0xffffffffu, m, o));

    // pass 2: denominator
    float den = 0.f;
    for (int j = beg + lane; j < end; j += 32) {
        float e = g_as[g_srcs[j]] + adn;
        e = (e > 0.f) ? e : 0.2f * e;
        den += __expf(e - m);
    }
#pragma unroll
    for (int o = 16; o; o >>= 1) den += __shfl_xor_sync(0xffffffffu, den, o);
    float inv = 1.0f / den;

    // pass 3: weighted aggregation; lane owns 4 of 128 dims
    float4 acc = make_float4(0.f, 0.f, 0.f, 0.f);
    for (int j = beg; j < end; ++j) {
        int s = g_srcs[j];
        float e = g_as[s] + adn;
        e = (e > 0.f) ? e : 0.2f * e;
        float wgt = __expf(e - m) * inv;
        float4 hv = g_h4[s * 32 + lane];
        acc.x += wgt * hv.x; acc.y += wgt * hv.y;
        acc.z += wgt * hv.z; acc.w += wgt * hv.w;
    }
    float b0 = bias[4 * lane + 0], b1 = bias[4 * lane + 1];
    float b2 = bias[4 * lane + 2], b3 = bias[4 * lane + 3];
    g_t4[w * 32 + lane] = make_float4(acc.x + b0, acc.y + b1, acc.z + b2, acc.w + b3);
}

// ============================ launch ============================
extern "C" void kernel_launch(void* const* d_in, const int* in_sizes, int n_in,
                              void* d_out, int out_size) {
    const float* x   = (const float*)d_in[0];
    const int*   ei  = (const int*)d_in[1];     // int32 (JAX x64-disabled)
    const float* W1  = (const float*)d_in[2];
    const float* a1s = (const float*)d_in[3];
    const float* a1d = (const float*)d_in[4];
    const float* b1  = (const float*)d_in[5];
    const float* W2  = (const float*)d_in[6];
    const float* a2s = (const float*)d_in[7];
    const float* a2d = (const float*)d_in[8];
    const float* b2  = (const float*)d_in[9];
    const float* fcw = (const float*)d_in[10];
    const float* fcb = (const float*)d_in[11];
    float*       out = (float*)d_out;
    int E = in_sizes[1] / 2;

    int gemm_blocks = (NN + 63) / 64;
    int agg_blocks  = (NN * 32 + 255) / 256;

    // CSR build (rebuilt every call; deterministic work)
    k_init_deg<<<(NN + 255) / 256, 256>>>();
    k_count<<<(E + 255) / 256, 256>>>(ei, E);
    k_scan<<<1, 1024>>>();
    k_self<<<(NN + 255) / 256, 256>>>();
    k_scatter<<<(E + 255) / 256, 256>>>(ei, E);

    // layer 1
    gemm_kernel<0><<<gemm_blocks, 256>>>((const float4*)x, W1, a1s, a1d, nullptr, nullptr);
    agg_kernel<<<agg_blocks, 256>>>(b1);
    // layer 2 (relu applied to input inside GEMM)
    gemm_kernel<1><<<gemm_blocks, 256>>>(nullptr, W2, a2s, a2d, nullptr, nullptr);
    agg_kernel<<<agg_blocks, 256>>>(b2);
    // output head
    gemm_kernel<2><<<gemm_blocks, 256>>>(nullptr, fcw, nullptr, nullptr, fcb, out);
}